// round 1
// baseline (speedup 1.0000x reference)
#include <cuda_runtime.h>
#include <math.h>

// Problem constants
#define BATCH 8
#define CDIM  512
#define LDIM  4096
#define HEADS 8
#define DIMH  64
#define HID   512   // HEADS*DIMH

// ---------------------------------------------------------------------------
// Scratch (static __device__ arrays: allocation-free, graph-capture safe)
// ---------------------------------------------------------------------------
__device__ float g_kv  [(size_t)BATCH * 2 * HID * LDIM];  // k rows 0..511, v rows 512..1023 per batch (134 MB)
__device__ float g_part[(size_t)8 * 64 * DIMH * DIMH];    // context split-K partials: [chunk][bh][64*64]
__device__ float g_ctx [(size_t)64 * DIMH * DIMH];        // context: [bh][d*64+e]
__device__ float g_Ab  [(size_t)BATCH * HID * CDIM];      // A_b
__device__ float g_Mb  [(size_t)BATCH * CDIM * CDIM];     // M_b = w_out @ A_b

// ---------------------------------------------------------------------------
// Generic tiled SGEMM: C[b] = A[b] (MxK, row-major) @ B[b] (KxN, row-major) + bias
// BM=BN=128, BK=8, 256 threads, 8x8 per thread. M%128==0, N%128==0, K%8==0.
// ---------------------------------------------------------------------------
__global__ __launch_bounds__(256, 2)
void sgemm128(const float* __restrict__ A, long lda_batch,
              const float* __restrict__ B, long ldb_batch,
              float* __restrict__ C, long ldc_batch,
              int M, int N, int K,
              const float* __restrict__ bias)
{
    const int BM = 128, BN = 128, BK = 8;
    A += (size_t)blockIdx.z * lda_batch;
    B += (size_t)blockIdx.z * ldb_batch;
    C += (size_t)blockIdx.z * ldc_batch;
    const int m0 = blockIdx.y * BM;
    const int n0 = blockIdx.x * BN;

    __shared__ __align__(16) float As[BK][BM];
    __shared__ __align__(16) float Bs[BK][BN];

    const int t = threadIdx.x;          // 0..255
    const int aRow  = t >> 1;           // 0..127
    const int aCol4 = (t & 1) * 4;      // 0 or 4
    const int bRow  = t >> 5;           // 0..7
    const int bCol4 = (t & 31) * 4;     // 0..124
    const int tx = t & 15, ty = t >> 4;

    float acc[8][8] = {};

    for (int k0 = 0; k0 < K; k0 += BK) {
        float4 a4 = *(const float4*)(A + (size_t)(m0 + aRow) * K + k0 + aCol4);
        As[aCol4 + 0][aRow] = a4.x;
        As[aCol4 + 1][aRow] = a4.y;
        As[aCol4 + 2][aRow] = a4.z;
        As[aCol4 + 3][aRow] = a4.w;
        *(float4*)(&Bs[bRow][bCol4]) =
            *(const float4*)(B + (size_t)(k0 + bRow) * N + n0 + bCol4);
        __syncthreads();

        #pragma unroll
        for (int kk = 0; kk < BK; kk++) {
            float ra[8], rb[8];
            *(float4*)(ra)     = *(const float4*)(&As[kk][ty * 8]);
            *(float4*)(ra + 4) = *(const float4*)(&As[kk][ty * 8 + 4]);
            *(float4*)(rb)     = *(const float4*)(&Bs[kk][tx * 8]);
            *(float4*)(rb + 4) = *(const float4*)(&Bs[kk][tx * 8 + 4]);
            #pragma unroll
            for (int i = 0; i < 8; i++)
                #pragma unroll
                for (int j = 0; j < 8; j++)
                    acc[i][j] = fmaf(ra[i], rb[j], acc[i][j]);
        }
        __syncthreads();
    }

    #pragma unroll
    for (int i = 0; i < 8; i++) {
        const int m = m0 + ty * 8 + i;
        const float bv = bias ? bias[m] : 0.0f;
        #pragma unroll
        for (int j = 0; j < 8; j += 4) {
            float4 o;
            o.x = acc[i][j + 0] + bv;
            o.y = acc[i][j + 1] + bv;
            o.z = acc[i][j + 2] + bv;
            o.w = acc[i][j + 3] + bv;
            *(float4*)(C + (size_t)m * N + n0 + tx * 8 + j) = o;
        }
    }
}

// ---------------------------------------------------------------------------
// Softmax over L=4096 for each of the 512 k-rows per batch (in place).
// grid = (512, BATCH), 256 threads, 16 elements/thread held in registers.
// ---------------------------------------------------------------------------
__global__ __launch_bounds__(256)
void softmax_k(float* __restrict__ kv)
{
    float* p = kv + (size_t)blockIdx.y * (2 * HID * LDIM)
                  + (size_t)blockIdx.x * LDIM;
    const int t = threadIdx.x;

    float buf[16];
    float m = -1e30f;
    #pragma unroll
    for (int c = 0; c < 4; c++) {
        float4 v = *(const float4*)(p + c * 1024 + t * 4);
        buf[c * 4 + 0] = v.x; buf[c * 4 + 1] = v.y;
        buf[c * 4 + 2] = v.z; buf[c * 4 + 3] = v.w;
        m = fmaxf(m, fmaxf(fmaxf(v.x, v.y), fmaxf(v.z, v.w)));
    }

    __shared__ float redmax[8];
    __shared__ float redsum[8];

    #pragma unroll
    for (int o = 16; o; o >>= 1) m = fmaxf(m, __shfl_xor_sync(0xffffffffu, m, o));
    if ((t & 31) == 0) redmax[t >> 5] = m;
    __syncthreads();
    m = redmax[0];
    #pragma unroll
    for (int i = 1; i < 8; i++) m = fmaxf(m, redmax[i]);

    float s = 0.0f;
    #pragma unroll
    for (int i = 0; i < 16; i++) { buf[i] = expf(buf[i] - m); s += buf[i]; }

    #pragma unroll
    for (int o = 16; o; o >>= 1) s += __shfl_xor_sync(0xffffffffu, s, o);
    if ((t & 31) == 0) redsum[t >> 5] = s;
    __syncthreads();
    s = 0.0f;
    #pragma unroll
    for (int i = 0; i < 8; i++) s += redsum[i];
    const float inv = 1.0f / s;

    #pragma unroll
    for (int c = 0; c < 4; c++) {
        float4 v;
        v.x = buf[c * 4 + 0] * inv; v.y = buf[c * 4 + 1] * inv;
        v.z = buf[c * 4 + 2] * inv; v.w = buf[c * 4 + 3] * inv;
        *(float4*)(p + c * 1024 + t * 4) = v;
    }
}

// ---------------------------------------------------------------------------
// Context partials: ctx[b,h,d,e] = sum_n k[d,n] * v[e,n], split-K over L into
// 8 chunks of 512. grid = (8 chunks, 64 bh), 256 threads, 4x4 per thread.
// ---------------------------------------------------------------------------
__global__ __launch_bounds__(256)
void context_partial(const float* __restrict__ kv, float* __restrict__ part)
{
    const int chunk = blockIdx.x;   // 0..7
    const int bh = blockIdx.y;      // 0..63
    const int b = bh >> 3, h = bh & 7;
    const float* kb = kv + (size_t)b * (2 * HID * LDIM) + (size_t)(h * 64) * LDIM + chunk * 512;
    const float* vb = kv + (size_t)b * (2 * HID * LDIM) + (size_t)(HID + h * 64) * LDIM + chunk * 512;

    __shared__ __align__(16) float Ks[32][68];  // [n][d], pad 68 -> 16B-aligned rows
    __shared__ __align__(16) float Vs[32][68];

    const int t = threadIdx.x;
    const int tx = t & 15, ty = t >> 4;
    float acc[4][4] = {};

    for (int n0 = 0; n0 < 512; n0 += 32) {
        #pragma unroll
        for (int r = 0; r < 2; r++) {
            const int idx = t + r * 256;   // 0..511
            const int d = idx >> 3;        // 0..63
            const int nf = idx & 7;        // float4 slot within 32-wide n tile
            float4 kvv = *(const float4*)(kb + (size_t)d * LDIM + n0 + nf * 4);
            Ks[nf * 4 + 0][d] = kvv.x; Ks[nf * 4 + 1][d] = kvv.y;
            Ks[nf * 4 + 2][d] = kvv.z; Ks[nf * 4 + 3][d] = kvv.w;
            float4 vv = *(const float4*)(vb + (size_t)d * LDIM + n0 + nf * 4);
            Vs[nf * 4 + 0][d] = vv.x; Vs[nf * 4 + 1][d] = vv.y;
            Vs[nf * 4 + 2][d] = vv.z; Vs[nf * 4 + 3][d] = vv.w;
        }
        __syncthreads();
        #pragma unroll
        for (int kk = 0; kk < 32; kk++) {
            float ra[4], rb[4];
            *(float4*)ra = *(const float4*)(&Ks[kk][ty * 4]);
            *(float4*)rb = *(const float4*)(&Vs[kk][tx * 4]);
            #pragma unroll
            for (int i = 0; i < 4; i++)
                #pragma unroll
                for (int j = 0; j < 4; j++)
                    acc[i][j] = fmaf(ra[i], rb[j], acc[i][j]);
        }
        __syncthreads();
    }

    float* pp = part + (size_t)(chunk * 64 + bh) * (DIMH * DIMH);
    #pragma unroll
    for (int i = 0; i < 4; i++)
        #pragma unroll
        for (int j = 0; j < 4; j++)
            pp[(ty * 4 + i) * 64 + tx * 4 + j] = acc[i][j];
}

__global__ void context_reduce(const float* __restrict__ part, float* __restrict__ ctx)
{
    const int bh = blockIdx.x;
    for (int i = threadIdx.x; i < DIMH * DIMH; i += blockDim.x) {
        float s = 0.0f;
        #pragma unroll
        for (int c = 0; c < 8; c++) s += part[(size_t)(c * 64 + bh) * (DIMH * DIMH) + i];
        ctx[(size_t)bh * (DIMH * DIMH) + i] = s;
    }
}

// ---------------------------------------------------------------------------
// A_b[(h,e),c] = sum_d ctx[b,h,d,e] * W_q[(h,d),c]
// grid = (8 c-chunks of 64, 64 bh), 256 threads.
// ---------------------------------------------------------------------------
__global__ __launch_bounds__(256)
void make_Ab(const float* __restrict__ ctx, const float* __restrict__ w_qkv,
             float* __restrict__ Ab)
{
    const int cc = blockIdx.x;    // c chunk
    const int bh = blockIdx.y;
    const int b = bh >> 3, h = bh & 7;

    __shared__ float Cs[64 * 64];     // ctx[d*64+e]
    __shared__ float Ws[64][65];      // W_q[d][c]

    const int t = threadIdx.x;
    const float* cp = ctx + (size_t)bh * (DIMH * DIMH);
    for (int i = t; i < 4096; i += 256) Cs[i] = cp[i];
    for (int i = t; i < 4096; i += 256) {
        const int d = i >> 6, c = i & 63;
        Ws[d][c] = w_qkv[(size_t)(h * 64 + d) * CDIM + cc * 64 + c];
    }
    __syncthreads();

    for (int i = t; i < 4096; i += 256) {
        const int e = i >> 6, c = i & 63;
        float s = 0.0f;
        #pragma unroll 8
        for (int d = 0; d < 64; d++) s = fmaf(Cs[d * 64 + e], Ws[d][c], s);
        Ab[(size_t)b * (HID * CDIM) + (size_t)(h * 64 + e) * CDIM + cc * 64 + c] = s;
    }
}

// ---------------------------------------------------------------------------
// Launch
// ---------------------------------------------------------------------------
extern "C" void kernel_launch(void* const* d_in, const int* in_sizes, int n_in,
                              void* d_out, int out_size)
{
    const float* x     = (const float*)d_in[0];   // (8, 512, 4096)
    const float* w_qkv = (const float*)d_in[1];   // (1536, 512)
    const float* w_out = (const float*)d_in[2];   // (512, 512)
    const float* b_out = (const float*)d_in[3];   // (512,)
    float* out = (float*)d_out;                   // (8, 512, 4096)

    float *kv, *part, *ctx, *Ab, *Mb;
    cudaGetSymbolAddress((void**)&kv,   g_kv);
    cudaGetSymbolAddress((void**)&part, g_part);
    cudaGetSymbolAddress((void**)&ctx,  g_ctx);
    cudaGetSymbolAddress((void**)&Ab,   g_Ab);
    cudaGetSymbolAddress((void**)&Mb,   g_Mb);

    const dim3 blk(256);
    const long sX  = (long)CDIM * LDIM;       // per-batch x stride
    const long sKV = (long)2 * HID * LDIM;    // per-batch kv stride

    // 1) kv[b] = W_kv(1024x512) @ x_b  (W_kv = rows 512..1535 of w_qkv)
    sgemm128<<<dim3(LDIM / 128, (2 * HID) / 128, BATCH), blk>>>(
        w_qkv + (size_t)HID * CDIM, 0L, x, sX, kv, sKV, 2 * HID, LDIM, CDIM, nullptr);

    // 2) softmax over L on the 512 k rows per batch
    softmax_k<<<dim3(HID, BATCH), blk>>>(kv);

    // 3) context with split-K over L, then reduce
    context_partial<<<dim3(8, 64), blk>>>(kv, part);
    context_reduce<<<64, blk>>>(part, ctx);

    // 4) A_b = BlockDiag(ctx^T) @ W_q
    make_Ab<<<dim3(8, 64), blk>>>(ctx, w_qkv, Ab);

    // 5) M_b = w_out @ A_b   (512x512x512 per batch)
    sgemm128<<<dim3(CDIM / 128, CDIM / 128, BATCH), blk>>>(
        w_out, 0L, Ab, (long)HID * CDIM, Mb, (long)CDIM * CDIM, CDIM, CDIM, HID, nullptr);

    // 6) out[b] = M_b @ x_b + b_out
    sgemm128<<<dim3(LDIM / 128, CDIM / 128, BATCH), blk>>>(
        Mb, (long)CDIM * CDIM, x, sX, out, sX, CDIM, LDIM, CDIM, b_out);
}

// round 3
// speedup vs baseline: 2.0355x; 2.0355x over previous
#include <cuda_runtime.h>
#include <cuda_bf16.h>
#include <math.h>
#include <stdint.h>

// Problem constants
#define BATCH 8
#define CDIM  512
#define LDIM  4096
#define HEADS 8
#define DIMH  64
#define HID   512   // HEADS*DIMH

// ---------------------------------------------------------------------------
// Scratch (static __device__ arrays: allocation-free, graph-capture safe)
// ---------------------------------------------------------------------------
__device__ float g_kv  [(size_t)BATCH * 2 * HID * LDIM];  // k rows 0..511, v rows 512..1023 per batch
__device__ float g_part[(size_t)8 * 64 * DIMH * DIMH];    // context split-K partials
__device__ float g_ctx [(size_t)64 * DIMH * DIMH];        // context: [bh][d*64+e]
__device__ float g_Ab  [(size_t)BATCH * HID * CDIM];      // A_b
__device__ float g_Mb  [(size_t)BATCH * CDIM * CDIM];     // M_b = w_out @ A_b

// bf16 split operands for tensor-core GEMMs
__device__ __nv_bfloat16 g_xT_hi[(size_t)BATCH * LDIM * CDIM];  // x transposed: [b][l][c]
__device__ __nv_bfloat16 g_xT_lo[(size_t)BATCH * LDIM * CDIM];
__device__ __nv_bfloat16 g_w_hi [(size_t)(2 * HID) * CDIM];     // W_kv rows
__device__ __nv_bfloat16 g_w_lo [(size_t)(2 * HID) * CDIM];
__device__ __nv_bfloat16 g_Mb_hi[(size_t)BATCH * CDIM * CDIM];
__device__ __nv_bfloat16 g_Mb_lo[(size_t)BATCH * CDIM * CDIM];

// ---------------------------------------------------------------------------
// Arch-portable async-copy / ldmatrix / mma.sync helpers (sm_80+, works on sm_103)
// ---------------------------------------------------------------------------
__device__ __forceinline__ uint32_t smem_u32(const void* p) {
    uint32_t a;
    asm("{ .reg .u64 t; cvta.to.shared.u64 t, %1; cvt.u32.u64 %0, t; }" : "=r"(a) : "l"(p));
    return a;
}
__device__ __forceinline__ void cp_async16(uint32_t dst, const void* src) {
    asm volatile("cp.async.cg.shared.global [%0], [%1], 16;" :: "r"(dst), "l"(src));
}
__device__ __forceinline__ void cp_commit() {
    asm volatile("cp.async.commit_group;" ::: "memory");
}
__device__ __forceinline__ void cp_wait1() {
    asm volatile("cp.async.wait_group 1;" ::: "memory");
}
__device__ __forceinline__ void cp_wait0() {
    asm volatile("cp.async.wait_group 0;" ::: "memory");
}
__device__ __forceinline__ void ldsm_x4(uint32_t* r, uint32_t addr) {
    asm volatile("ldmatrix.sync.aligned.m8n8.x4.shared.b16 {%0,%1,%2,%3}, [%4];"
                 : "=r"(r[0]), "=r"(r[1]), "=r"(r[2]), "=r"(r[3]) : "r"(addr));
}
__device__ __forceinline__ void ldsm_x2(uint32_t* r, uint32_t addr) {
    asm volatile("ldmatrix.sync.aligned.m8n8.x2.shared.b16 {%0,%1}, [%2];"
                 : "=r"(r[0]), "=r"(r[1]) : "r"(addr));
}
__device__ __forceinline__ void mma_bf16(float* c, const uint32_t* a, const uint32_t* b) {
    asm volatile(
        "mma.sync.aligned.m16n8k16.row.col.f32.bf16.bf16.f32 "
        "{%0,%1,%2,%3}, {%4,%5,%6,%7}, {%8,%9}, {%0,%1,%2,%3};"
        : "+f"(c[0]), "+f"(c[1]), "+f"(c[2]), "+f"(c[3])
        : "r"(a[0]), "r"(a[1]), "r"(a[2]), "r"(a[3]), "r"(b[0]), "r"(b[1]));
}

// ---------------------------------------------------------------------------
// tc_gemm (mma.sync version):
// C[b][m][n] (+bias[m]) = sum_k (Ahi+Alo)[m,k]*(Bhi+Blo)[n,k], K=512,
// A/B row stride 512 (bf16), C row stride 4096 (fp32).
// CTA tile 128x128, K-chunk 64, 8 warps (2Mx4N), warp tile 64x32,
// cp.async double-buffered, split-bf16 (3 MMAs).
// ---------------------------------------------------------------------------
#define ROWB   144            // padded smem row: 64 bf16 (128B) + 16B pad
#define MATB   (128 * ROWB)   // 18432 B per matrix tile
#define BUFB   (4 * MATB)     // Ah, Al, Bh, Bl
#define TCG_SMEM (2 * BUFB)   // 147456 B

__global__ __launch_bounds__(256, 1)
void tc_gemm(const __nv_bfloat16* __restrict__ Ahi, const __nv_bfloat16* __restrict__ Alo,
             long aStride,
             const __nv_bfloat16* __restrict__ Bhi, const __nv_bfloat16* __restrict__ Blo,
             long bStride,
             float* __restrict__ Cp, long cStride,
             const float* __restrict__ bias)
{
    extern __shared__ char smem[];
    const uint32_t sb = smem_u32(smem);
    const int t = threadIdx.x;
    const int lane = t & 31;
    const int warp = t >> 5;
    const int wm = (warp & 1) * 64;    // warp M offset within CTA tile
    const int wn = (warp >> 1) * 32;   // warp N offset
    const int n0 = blockIdx.x * 128;
    const int m0 = blockIdx.y * 128;
    const int b = blockIdx.z;

    Ahi += (size_t)b * aStride;  Alo += (size_t)b * aStride;
    Bhi += (size_t)b * bStride;  Blo += (size_t)b * bStride;
    Cp  += (size_t)b * cStride;

    // per-thread ldmatrix base addresses (byte offsets within a matrix tile)
    // A (x4): lane -> row (lane%16), half-col block (lane/16)*8 halves = *16B
    const uint32_t aOff = (uint32_t)((lane & 15) * ROWB + (lane >> 4) * 16);
    // B (x2): lane -> row (lane%8), halves block ((lane>>3)&1)*8 -> *16B
    const uint32_t bOff = (uint32_t)((lane & 7) * ROWB + ((lane >> 3) & 1) * 16);

    float acc[4][4][4] = {};   // [mt][nt][reg]

    // ---- async load of one K-chunk into buffer ----
    auto load_chunk = [&](int c, int buf) {
        const int k0 = c * 64;
        const uint32_t base = sb + (uint32_t)buf * BUFB;
        #pragma unroll
        for (int i = 0; i < 4; i++) {
            const int idx = t + i * 256;        // 0..1023
            const int r = idx >> 3;             // 0..127
            const int s = idx & 7;              // 16B segment
            const uint32_t dst = base + (uint32_t)(r * ROWB + s * 16);
            const size_t ga = (size_t)(m0 + r) * 512 + k0 + s * 8;
            const size_t gb = (size_t)(n0 + r) * 512 + k0 + s * 8;
            cp_async16(dst,            Ahi + ga);
            cp_async16(dst + MATB,     Alo + ga);
            cp_async16(dst + 2 * MATB, Bhi + gb);
            cp_async16(dst + 3 * MATB, Blo + gb);
        }
    };

    load_chunk(0, 0);
    cp_commit();

    for (int c = 0; c < 8; c++) {
        if (c < 7) { load_chunk(c + 1, (c + 1) & 1); cp_commit(); cp_wait1(); }
        else       { cp_wait0(); }
        __syncthreads();

        const uint32_t base = sb + (uint32_t)(c & 1) * BUFB;
        #pragma unroll
        for (int ks = 0; ks < 4; ks++) {           // 4 x k16 per 64-chunk
            const uint32_t kb = (uint32_t)(ks * 32);  // 16 halves = 32B
            uint32_t ah[4][4], al[4][4];
            #pragma unroll
            for (int mt = 0; mt < 4; mt++) {
                const uint32_t ra = base + (uint32_t)((wm + mt * 16) * ROWB) + aOff + kb;
                ldsm_x4(ah[mt], ra);
                ldsm_x4(al[mt], ra + MATB);
            }
            uint32_t bh[4][2], bl[4][2];
            #pragma unroll
            for (int nt = 0; nt < 4; nt++) {
                const uint32_t rb = base + 2 * MATB + (uint32_t)((wn + nt * 8) * ROWB) + bOff + kb;
                ldsm_x2(bh[nt], rb);
                ldsm_x2(bl[nt], rb + MATB);
            }
            #pragma unroll
            for (int mt = 0; mt < 4; mt++)
                #pragma unroll
                for (int nt = 0; nt < 4; nt++) {
                    mma_bf16(acc[mt][nt], ah[mt], bh[nt]);
                    mma_bf16(acc[mt][nt], ah[mt], bl[nt]);
                    mma_bf16(acc[mt][nt], al[mt], bh[nt]);
                }
        }
        __syncthreads();
    }

    // ---- epilogue ----
    #pragma unroll
    for (int mt = 0; mt < 4; mt++) {
        const int row = m0 + wm + mt * 16 + (lane >> 2);
        const float bv0 = bias ? bias[row] : 0.0f;
        const float bv1 = bias ? bias[row + 8] : 0.0f;
        #pragma unroll
        for (int nt = 0; nt < 4; nt++) {
            const int col = n0 + wn + nt * 8 + 2 * (lane & 3);
            float2 o0 = make_float2(acc[mt][nt][0] + bv0, acc[mt][nt][1] + bv0);
            float2 o1 = make_float2(acc[mt][nt][2] + bv1, acc[mt][nt][3] + bv1);
            *(float2*)(Cp + (size_t)row * 4096 + col)       = o0;
            *(float2*)(Cp + (size_t)(row + 8) * 4096 + col) = o1;
        }
    }
}

// ---------------------------------------------------------------------------
// Conversion kernels
// ---------------------------------------------------------------------------
__global__ __launch_bounds__(256)
void conv_split(const float* __restrict__ in, __nv_bfloat16* __restrict__ hi,
                __nv_bfloat16* __restrict__ lo, int n)
{
    int i = blockIdx.x * 256 + threadIdx.x;
    if (i >= n) return;
    float v = in[i];
    __nv_bfloat16 h = __float2bfloat16(v);
    hi[i] = h;
    lo[i] = __float2bfloat16(v - __bfloat162float(h));
}

// x[b][c][l] -> xT hi/lo [b][l][c]  (32x32 smem tiles)
__global__ __launch_bounds__(256)
void conv_xT(const float* __restrict__ x, __nv_bfloat16* __restrict__ xh,
             __nv_bfloat16* __restrict__ xl)
{
    __shared__ float tile[32][33];
    const int l0 = blockIdx.x * 32, c0 = blockIdx.y * 32, b = blockIdx.z;
    const float* xb = x + (size_t)b * CDIM * LDIM;
    const int tr = threadIdx.x >> 5;
    const int tc = threadIdx.x & 31;

    #pragma unroll
    for (int i = 0; i < 4; i++) {
        const int c = tr + i * 8;
        tile[c][tc] = xb[(size_t)(c0 + c) * LDIM + l0 + tc];
    }
    __syncthreads();

    __nv_bfloat16* oh = xh + (size_t)b * LDIM * CDIM;
    __nv_bfloat16* ol = xl + (size_t)b * LDIM * CDIM;
    #pragma unroll
    for (int i = 0; i < 4; i++) {
        const int l = tr + i * 8;
        const float v = tile[tc][l];
        const __nv_bfloat16 h = __float2bfloat16(v);
        oh[(size_t)(l0 + l) * CDIM + c0 + tc] = h;
        ol[(size_t)(l0 + l) * CDIM + c0 + tc] = __float2bfloat16(v - __bfloat162float(h));
    }
}

// ---------------------------------------------------------------------------
// SIMT SGEMM (GEMM2), softmax, context, make_Ab — unchanged from passing R1
// ---------------------------------------------------------------------------
__global__ __launch_bounds__(256, 2)
void sgemm128(const float* __restrict__ A, long lda_batch,
              const float* __restrict__ B, long ldb_batch,
              float* __restrict__ C, long ldc_batch,
              int M, int N, int K,
              const float* __restrict__ bias)
{
    const int BM = 128, BN = 128, BK = 8;
    A += (size_t)blockIdx.z * lda_batch;
    B += (size_t)blockIdx.z * ldb_batch;
    C += (size_t)blockIdx.z * ldc_batch;
    const int m0 = blockIdx.y * BM;
    const int n0 = blockIdx.x * BN;

    __shared__ __align__(16) float As[BK][BM];
    __shared__ __align__(16) float Bs[BK][BN];

    const int t = threadIdx.x;
    const int aRow  = t >> 1;
    const int aCol4 = (t & 1) * 4;
    const int bRow  = t >> 5;
    const int bCol4 = (t & 31) * 4;
    const int tx = t & 15, ty = t >> 4;

    float acc[8][8] = {};

    for (int k0 = 0; k0 < K; k0 += BK) {
        float4 a4 = *(const float4*)(A + (size_t)(m0 + aRow) * K + k0 + aCol4);
        As[aCol4 + 0][aRow] = a4.x;
        As[aCol4 + 1][aRow] = a4.y;
        As[aCol4 + 2][aRow] = a4.z;
        As[aCol4 + 3][aRow] = a4.w;
        *(float4*)(&Bs[bRow][bCol4]) =
            *(const float4*)(B + (size_t)(k0 + bRow) * N + n0 + bCol4);
        __syncthreads();

        #pragma unroll
        for (int kk = 0; kk < BK; kk++) {
            float ra[8], rb[8];
            *(float4*)(ra)     = *(const float4*)(&As[kk][ty * 8]);
            *(float4*)(ra + 4) = *(const float4*)(&As[kk][ty * 8 + 4]);
            *(float4*)(rb)     = *(const float4*)(&Bs[kk][tx * 8]);
            *(float4*)(rb + 4) = *(const float4*)(&Bs[kk][tx * 8 + 4]);
            #pragma unroll
            for (int i = 0; i < 8; i++)
                #pragma unroll
                for (int j = 0; j < 8; j++)
                    acc[i][j] = fmaf(ra[i], rb[j], acc[i][j]);
        }
        __syncthreads();
    }

    #pragma unroll
    for (int i = 0; i < 8; i++) {
        const int m = m0 + ty * 8 + i;
        const float bv = bias ? bias[m] : 0.0f;
        #pragma unroll
        for (int j = 0; j < 8; j += 4) {
            float4 o;
            o.x = acc[i][j + 0] + bv;
            o.y = acc[i][j + 1] + bv;
            o.z = acc[i][j + 2] + bv;
            o.w = acc[i][j + 3] + bv;
            *(float4*)(C + (size_t)m * N + n0 + tx * 8 + j) = o;
        }
    }
}

__global__ __launch_bounds__(256)
void softmax_k(float* __restrict__ kv)
{
    float* p = kv + (size_t)blockIdx.y * (2 * HID * LDIM)
                  + (size_t)blockIdx.x * LDIM;
    const int t = threadIdx.x;

    float buf[16];
    float m = -1e30f;
    #pragma unroll
    for (int c = 0; c < 4; c++) {
        float4 v = *(const float4*)(p + c * 1024 + t * 4);
        buf[c * 4 + 0] = v.x; buf[c * 4 + 1] = v.y;
        buf[c * 4 + 2] = v.z; buf[c * 4 + 3] = v.w;
        m = fmaxf(m, fmaxf(fmaxf(v.x, v.y), fmaxf(v.z, v.w)));
    }

    __shared__ float redmax[8];
    __shared__ float redsum[8];

    #pragma unroll
    for (int o = 16; o; o >>= 1) m = fmaxf(m, __shfl_xor_sync(0xffffffffu, m, o));
    if ((t & 31) == 0) redmax[t >> 5] = m;
    __syncthreads();
    m = redmax[0];
    #pragma unroll
    for (int i = 1; i < 8; i++) m = fmaxf(m, redmax[i]);

    float s = 0.0f;
    #pragma unroll
    for (int i = 0; i < 16; i++) { buf[i] = expf(buf[i] - m); s += buf[i]; }

    #pragma unroll
    for (int o = 16; o; o >>= 1) s += __shfl_xor_sync(0xffffffffu, s, o);
    if ((t & 31) == 0) redsum[t >> 5] = s;
    __syncthreads();
    s = 0.0f;
    #pragma unroll
    for (int i = 0; i < 8; i++) s += redsum[i];
    const float inv = 1.0f / s;

    #pragma unroll
    for (int c = 0; c < 4; c++) {
        float4 v;
        v.x = buf[c * 4 + 0] * inv; v.y = buf[c * 4 + 1] * inv;
        v.z = buf[c * 4 + 2] * inv; v.w = buf[c * 4 + 3] * inv;
        *(float4*)(p + c * 1024 + t * 4) = v;
    }
}

__global__ __launch_bounds__(256)
void context_partial(const float* __restrict__ kv, float* __restrict__ part)
{
    const int chunk = blockIdx.x;
    const int bh = blockIdx.y;
    const int b = bh >> 3, h = bh & 7;
    const float* kb = kv + (size_t)b * (2 * HID * LDIM) + (size_t)(h * 64) * LDIM + chunk * 512;
    const float* vb = kv + (size_t)b * (2 * HID * LDIM) + (size_t)(HID + h * 64) * LDIM + chunk * 512;

    __shared__ __align__(16) float Ks[32][68];
    __shared__ __align__(16) float Vs[32][68];

    const int t = threadIdx.x;
    const int tx = t & 15, ty = t >> 4;
    float acc[4][4] = {};

    for (int n0 = 0; n0 < 512; n0 += 32) {
        #pragma unroll
        for (int r = 0; r < 2; r++) {
            const int idx = t + r * 256;
            const int d = idx >> 3;
            const int nf = idx & 7;
            float4 kvv = *(const float4*)(kb + (size_t)d * LDIM + n0 + nf * 4);
            Ks[nf * 4 + 0][d] = kvv.x; Ks[nf * 4 + 1][d] = kvv.y;
            Ks[nf * 4 + 2][d] = kvv.z; Ks[nf * 4 + 3][d] = kvv.w;
            float4 vv = *(const float4*)(vb + (size_t)d * LDIM + n0 + nf * 4);
            Vs[nf * 4 + 0][d] = vv.x; Vs[nf * 4 + 1][d] = vv.y;
            Vs[nf * 4 + 2][d] = vv.z; Vs[nf * 4 + 3][d] = vv.w;
        }
        __syncthreads();
        #pragma unroll
        for (int kk = 0; kk < 32; kk++) {
            float ra[4], rb[4];
            *(float4*)ra = *(const float4*)(&Ks[kk][ty * 4]);
            *(float4*)rb = *(const float4*)(&Vs[kk][tx * 4]);
            #pragma unroll
            for (int i = 0; i < 4; i++)
                #pragma unroll
                for (int j = 0; j < 4; j++)
                    acc[i][j] = fmaf(ra[i], rb[j], acc[i][j]);
        }
        __syncthreads();
    }

    float* pp = part + (size_t)(chunk * 64 + bh) * (DIMH * DIMH);
    #pragma unroll
    for (int i = 0; i < 4; i++)
        #pragma unroll
        for (int j = 0; j < 4; j++)
            pp[(ty * 4 + i) * 64 + tx * 4 + j] = acc[i][j];
}

__global__ void context_reduce(const float* __restrict__ part, float* __restrict__ ctx)
{
    const int bh = blockIdx.x;
    for (int i = threadIdx.x; i < DIMH * DIMH; i += blockDim.x) {
        float s = 0.0f;
        #pragma unroll
        for (int c = 0; c < 8; c++) s += part[(size_t)(c * 64 + bh) * (DIMH * DIMH) + i];
        ctx[(size_t)bh * (DIMH * DIMH) + i] = s;
    }
}

__global__ __launch_bounds__(256)
void make_Ab(const float* __restrict__ ctx, const float* __restrict__ w_qkv,
             float* __restrict__ Ab)
{
    const int cc = blockIdx.x;
    const int bh = blockIdx.y;
    const int b = bh >> 3, h = bh & 7;

    __shared__ float Cs[64 * 64];
    __shared__ float Ws[64][65];

    const int t = threadIdx.x;
    const float* cp = ctx + (size_t)bh * (DIMH * DIMH);
    for (int i = t; i < 4096; i += 256) Cs[i] = cp[i];
    for (int i = t; i < 4096; i += 256) {
        const int d = i >> 6, c = i & 63;
        Ws[d][c] = w_qkv[(size_t)(h * 64 + d) * CDIM + cc * 64 + c];
    }
    __syncthreads();

    for (int i = t; i < 4096; i += 256) {
        const int e = i >> 6, c = i & 63;
        float s = 0.0f;
        #pragma unroll 8
        for (int d = 0; d < 64; d++) s = fmaf(Cs[d * 64 + e], Ws[d][c], s);
        Ab[(size_t)b * (HID * CDIM) + (size_t)(h * 64 + e) * CDIM + cc * 64 + c] = s;
    }
}

// ---------------------------------------------------------------------------
// Launch
// ---------------------------------------------------------------------------
extern "C" void kernel_launch(void* const* d_in, const int* in_sizes, int n_in,
                              void* d_out, int out_size)
{
    const float* x     = (const float*)d_in[0];   // (8, 512, 4096)
    const float* w_qkv = (const float*)d_in[1];   // (1536, 512)
    const float* w_out = (const float*)d_in[2];   // (512, 512)
    const float* b_out = (const float*)d_in[3];   // (512,)
    float* out = (float*)d_out;                   // (8, 512, 4096)

    float *kv, *part, *ctx, *Ab, *Mb;
    __nv_bfloat16 *xTh, *xTl, *wh, *wl, *Mbh, *Mbl;
    cudaGetSymbolAddress((void**)&kv,   g_kv);
    cudaGetSymbolAddress((void**)&part, g_part);
    cudaGetSymbolAddress((void**)&ctx,  g_ctx);
    cudaGetSymbolAddress((void**)&Ab,   g_Ab);
    cudaGetSymbolAddress((void**)&Mb,   g_Mb);
    cudaGetSymbolAddress((void**)&xTh,  g_xT_hi);
    cudaGetSymbolAddress((void**)&xTl,  g_xT_lo);
    cudaGetSymbolAddress((void**)&wh,   g_w_hi);
    cudaGetSymbolAddress((void**)&wl,   g_w_lo);
    cudaGetSymbolAddress((void**)&Mbh,  g_Mb_hi);
    cudaGetSymbolAddress((void**)&Mbl,  g_Mb_lo);

    cudaFuncSetAttribute(tc_gemm, cudaFuncAttributeMaxDynamicSharedMemorySize, TCG_SMEM);

    const dim3 blk(256);
    const long sX  = (long)CDIM * LDIM;
    const long sKV = (long)2 * HID * LDIM;
    const long sXT = (long)LDIM * CDIM;

    // 0) split-bf16 conversions
    conv_split<<<(2 * HID * CDIM + 255) / 256, blk>>>(
        w_qkv + (size_t)HID * CDIM, wh, wl, 2 * HID * CDIM);
    conv_xT<<<dim3(LDIM / 32, CDIM / 32, BATCH), blk>>>(x, xTh, xTl);

    // 1) kv[b] = W_kv @ x_b  (mma.sync, split bf16)
    tc_gemm<<<dim3(LDIM / 128, (2 * HID) / 128, BATCH), blk, TCG_SMEM>>>(
        wh, wl, 0L, xTh, xTl, sXT, kv, sKV, nullptr);

    // 2) softmax over L on the 512 k rows per batch
    softmax_k<<<dim3(HID, BATCH), blk>>>(kv);

    // 3) context with split-K over L, then reduce
    context_partial<<<dim3(8, 64), blk>>>(kv, part);
    context_reduce<<<64, blk>>>(part, ctx);

    // 4) A_b = BlockDiag(ctx^T) @ W_q
    make_Ab<<<dim3(8, 64), blk>>>(ctx, w_qkv, Ab);

    // 5) M_b = w_out @ A_b   (512x512x512 per batch, SIMT)
    sgemm128<<<dim3(CDIM / 128, CDIM / 128, BATCH), blk>>>(
        w_out, 0L, Ab, (long)HID * CDIM, Mb, (long)CDIM * CDIM, CDIM, CDIM, HID, nullptr);

    // 5b) split M_b to bf16
    conv_split<<<(BATCH * CDIM * CDIM + 255) / 256, blk>>>(
        Mb, Mbh, Mbl, BATCH * CDIM * CDIM);

    // 6) out[b] = M_b @ x_b + b_out  (mma.sync, split bf16)
    tc_gemm<<<dim3(LDIM / 128, CDIM / 128, BATCH), blk, TCG_SMEM>>>(
        Mbh, Mbl, (long)CDIM * CDIM, xTh, xTl, sXT, out, sX, b_out);
}

// round 4
// speedup vs baseline: 2.8303x; 1.3905x over previous
#include <cuda_runtime.h>
#include <cuda_fp16.h>
#include <math.h>
#include <stdint.h>

// Problem constants
#define BATCH 8
#define CDIM  512
#define LDIM  4096
#define HEADS 8
#define DIMH  64
#define HID   512   // HEADS*DIMH

// ---------------------------------------------------------------------------
// Scratch (static __device__ arrays: allocation-free, graph-capture safe)
// ---------------------------------------------------------------------------
__device__ float g_kv  [(size_t)BATCH * 2 * HID * LDIM];  // k rows 0..511, v rows 512..1023 per batch
__device__ float g_part[(size_t)8 * 64 * DIMH * DIMH];    // context split-K partials
__device__ float g_ctx [(size_t)64 * DIMH * DIMH];        // context: [bh][d*64+e]

__device__ __half g_xT  [(size_t)BATCH * LDIM * CDIM];    // fp16(x) transposed: [b][l][c]
__device__ __half g_wk_h[(size_t)(2 * HID) * CDIM];       // fp16(64*W_kv) hi
__device__ __half g_wk_l[(size_t)(2 * HID) * CDIM];       // lo
__device__ __half g_wo_h[(size_t)CDIM * HID];             // fp16(64*W_out) hi
__device__ __half g_wo_l[(size_t)CDIM * HID];
__device__ __half g_Abt [(size_t)BATCH * CDIM * HID];     // fp16(A_b^T): [b][c][hid]
__device__ __half g_Mb_h[(size_t)BATCH * CDIM * CDIM];    // fp16(2048*M_b) hi
__device__ __half g_Mb_l[(size_t)BATCH * CDIM * CDIM];    // lo

// ---------------------------------------------------------------------------
// PTX helpers (arch-portable: cp.async / ldmatrix / mma.sync fp16)
// ---------------------------------------------------------------------------
__device__ __forceinline__ uint32_t smem_u32(const void* p) {
    uint32_t a;
    asm("{ .reg .u64 t; cvta.to.shared.u64 t, %1; cvt.u32.u64 %0, t; }" : "=r"(a) : "l"(p));
    return a;
}
__device__ __forceinline__ void cp_async16(uint32_t dst, const void* src) {
    asm volatile("cp.async.cg.shared.global [%0], [%1], 16;" :: "r"(dst), "l"(src));
}
__device__ __forceinline__ void cp_commit() { asm volatile("cp.async.commit_group;" ::: "memory"); }
__device__ __forceinline__ void cp_wait1()  { asm volatile("cp.async.wait_group 1;" ::: "memory"); }
__device__ __forceinline__ void cp_wait0()  { asm volatile("cp.async.wait_group 0;" ::: "memory"); }
__device__ __forceinline__ void ldsm_x4(uint32_t* r, uint32_t addr) {
    asm volatile("ldmatrix.sync.aligned.m8n8.x4.shared.b16 {%0,%1,%2,%3}, [%4];"
                 : "=r"(r[0]), "=r"(r[1]), "=r"(r[2]), "=r"(r[3]) : "r"(addr));
}
__device__ __forceinline__ void mma_fp16(float* c, const uint32_t* a, const uint32_t* b) {
    asm volatile(
        "mma.sync.aligned.m16n8k16.row.col.f32.f16.f16.f32 "
        "{%0,%1,%2,%3}, {%4,%5,%6,%7}, {%8,%9}, {%0,%1,%2,%3};"
        : "+f"(c[0]), "+f"(c[1]), "+f"(c[2]), "+f"(c[3])
        : "r"(a[0]), "r"(a[1]), "r"(a[2]), "r"(a[3]), "r"(b[0]), "r"(b[1]));
}

// ---------------------------------------------------------------------------
// tc2: C[b][m][n] = sum_k (Ah+Al)[m,k] * Bh[n,k]   (fp16 2-term split, K=512)
// A/B row stride = 512 halves. CTA tile 128x256, K-chunk 64, 8 warps (2Mx4N),
// warp tile 64x64, cp.async double-buffered.
// MODE 0: Cf[m*cRow+n] = acc*invScale (+bias[m])
// MODE 1: Ch/Cl fp16 split of acc*hScale (row stride cRow)
// ---------------------------------------------------------------------------
#define ROWB   144
#define A_MAT  (128 * ROWB)      // 18432
#define B_MAT  (256 * ROWB)      // 36864
#define STAGE  (2 * A_MAT + B_MAT)  // 73728
#define TC_SMEM (2 * STAGE)      // 147456

template<int MODE>
__global__ __launch_bounds__(256, 1)
void tc2(const __half* __restrict__ Ah, const __half* __restrict__ Al, long aBatch,
         const __half* __restrict__ Bh, long bBatch,
         float* __restrict__ Cf, __half* __restrict__ Ch, __half* __restrict__ Cl,
         long cBatch, int cRow,
         const float* __restrict__ bias, float invScale, float hScale)
{
    extern __shared__ char smem[];
    const uint32_t sb = smem_u32(smem);
    const int t = threadIdx.x;
    const int lane = t & 31;
    const int warp = t >> 5;
    const int wm = (warp & 1) * 64;     // warp M offset
    const int wn = (warp >> 1) * 64;    // warp N offset
    const int n0 = blockIdx.x * 256;
    const int m0 = blockIdx.y * 128;
    const int b = blockIdx.z;

    Ah += (size_t)b * aBatch;  Al += (size_t)b * aBatch;
    Bh += (size_t)b * bBatch;

    // ldmatrix per-lane offsets
    const uint32_t aOff = (uint32_t)((lane & 15) * ROWB + (lane >> 4) * 16);
    const uint32_t bOff = (uint32_t)(((lane & 7) + ((lane >> 4) << 3)) * ROWB
                                     + (((lane >> 3) & 1) * 16));

    float acc[4][8][4] = {};   // [mt][nt][reg]

    auto load_chunk = [&](int c, int buf) {
        const int k0 = c * 64;
        const uint32_t base = sb + (uint32_t)buf * STAGE;
        #pragma unroll
        for (int i = 0; i < 4; i++) {           // A hi+lo: 2048 segs
            const int idx = t + i * 256;        // 0..1023
            const int r = idx >> 3, s = idx & 7;
            const uint32_t dst = base + (uint32_t)(r * ROWB + s * 16);
            const size_t ga = (size_t)(m0 + r) * 512 + k0 + s * 8;
            cp_async16(dst,         Ah + ga);
            cp_async16(dst + A_MAT, Al + ga);
        }
        #pragma unroll
        for (int i = 0; i < 8; i++) {           // B: 2048 segs
            const int idx = t + i * 256;        // 0..2047
            const int r = idx >> 3, s = idx & 7;
            const uint32_t dst = base + 2 * A_MAT + (uint32_t)(r * ROWB + s * 16);
            cp_async16(dst, Bh + (size_t)(n0 + r) * 512 + k0 + s * 8);
        }
    };

    load_chunk(0, 0);
    cp_commit();

    for (int c = 0; c < 8; c++) {
        if (c < 7) { load_chunk(c + 1, (c + 1) & 1); cp_commit(); cp_wait1(); }
        else       { cp_wait0(); }
        __syncthreads();

        const uint32_t base = sb + (uint32_t)(c & 1) * STAGE;
        #pragma unroll
        for (int ks = 0; ks < 4; ks++) {
            const uint32_t kb = (uint32_t)(ks * 32);
            uint32_t ah[4][4], al[4][4];
            #pragma unroll
            for (int mt = 0; mt < 4; mt++) {
                const uint32_t ra = base + (uint32_t)((wm + mt * 16) * ROWB) + aOff + kb;
                ldsm_x4(ah[mt], ra);
                ldsm_x4(al[mt], ra + A_MAT);
            }
            uint32_t bfr[8][2];
            #pragma unroll
            for (int np = 0; np < 4; np++) {
                uint32_t r4[4];
                const uint32_t rb = base + 2 * A_MAT
                    + (uint32_t)((wn + np * 16) * ROWB) + bOff + kb;
                ldsm_x4(r4, rb);
                bfr[np * 2][0] = r4[0]; bfr[np * 2][1] = r4[1];
                bfr[np * 2 + 1][0] = r4[2]; bfr[np * 2 + 1][1] = r4[3];
            }
            #pragma unroll
            for (int mt = 0; mt < 4; mt++)
                #pragma unroll
                for (int nt = 0; nt < 8; nt++) {
                    mma_fp16(acc[mt][nt], ah[mt], bfr[nt]);
                    mma_fp16(acc[mt][nt], al[mt], bfr[nt]);
                }
        }
        __syncthreads();
    }

    // ---- epilogue ----
    #pragma unroll
    for (int mt = 0; mt < 4; mt++) {
        const int row = m0 + wm + mt * 16 + (lane >> 2);
        float bv0 = 0.0f, bv1 = 0.0f;
        if (MODE == 0 && bias) { bv0 = bias[row]; bv1 = bias[row + 8]; }
        #pragma unroll
        for (int nt = 0; nt < 8; nt++) {
            const int col = n0 + wn + nt * 8 + 2 * (lane & 3);
            if (MODE == 0) {
                float* c0 = Cf + (size_t)b * cBatch + (size_t)row * cRow + col;
                float* c1 = Cf + (size_t)b * cBatch + (size_t)(row + 8) * cRow + col;
                *(float2*)c0 = make_float2(acc[mt][nt][0] * invScale + bv0,
                                           acc[mt][nt][1] * invScale + bv0);
                *(float2*)c1 = make_float2(acc[mt][nt][2] * invScale + bv1,
                                           acc[mt][nt][3] * invScale + bv1);
            } else {
                #pragma unroll
                for (int half_ : {0, 1}) {
                    const int rr = row + half_ * 8;
                    const float v0 = acc[mt][nt][half_ * 2 + 0] * hScale;
                    const float v1 = acc[mt][nt][half_ * 2 + 1] * hScale;
                    const __half h0 = __float2half_rn(v0);
                    const __half h1 = __float2half_rn(v1);
                    const __half l0 = __float2half_rn(v0 - __half2float(h0));
                    const __half l1 = __float2half_rn(v1 - __half2float(h1));
                    const size_t o = (size_t)b * cBatch + (size_t)rr * cRow + col;
                    *(__half2*)(Ch + o) = __halves2half2(h0, h1);
                    *(__half2*)(Cl + o) = __halves2half2(l0, l1);
                }
            }
        }
    }
}

// ---------------------------------------------------------------------------
// Conversions
// ---------------------------------------------------------------------------
// scaled fp16 split of fp32 weights: h = fp16(64 v), l = fp16(64 v - h)
__global__ __launch_bounds__(256)
void conv_wsplit(const float* __restrict__ in, __half* __restrict__ hi,
                 __half* __restrict__ lo, int n)
{
    int i = blockIdx.x * 256 + threadIdx.x;
    if (i >= n) return;
    float v = in[i] * 64.0f;
    __half h = __float2half_rn(v);
    hi[i] = h;
    lo[i] = __float2half_rn(v - __half2float(h));
}

// x[b][c][l] -> fp16 xT [b][l][c]
__global__ __launch_bounds__(256)
void conv_xT(const float* __restrict__ x, __half* __restrict__ xh)
{
    __shared__ float tile[32][33];
    const int l0 = blockIdx.x * 32, c0 = blockIdx.y * 32, b = blockIdx.z;
    const float* xb = x + (size_t)b * CDIM * LDIM;
    const int tr = threadIdx.x >> 5;
    const int tc = threadIdx.x & 31;

    #pragma unroll
    for (int i = 0; i < 4; i++) {
        const int c = tr + i * 8;
        tile[c][tc] = xb[(size_t)(c0 + c) * LDIM + l0 + tc];
    }
    __syncthreads();

    __half* oh = xh + (size_t)b * LDIM * CDIM;
    #pragma unroll
    for (int i = 0; i < 4; i++) {
        const int l = tr + i * 8;
        oh[(size_t)(l0 + l) * CDIM + c0 + tc] = __float2half_rn(tile[tc][l]);
    }
}

// ---------------------------------------------------------------------------
// softmax / context / make_Ab
// ---------------------------------------------------------------------------
__global__ __launch_bounds__(256)
void softmax_k(float* __restrict__ kv)
{
    float* p = kv + (size_t)blockIdx.y * (2 * HID * LDIM)
                  + (size_t)blockIdx.x * LDIM;
    const int t = threadIdx.x;

    float buf[16];
    float m = -1e30f;
    #pragma unroll
    for (int c = 0; c < 4; c++) {
        float4 v = *(const float4*)(p + c * 1024 + t * 4);
        buf[c * 4 + 0] = v.x; buf[c * 4 + 1] = v.y;
        buf[c * 4 + 2] = v.z; buf[c * 4 + 3] = v.w;
        m = fmaxf(m, fmaxf(fmaxf(v.x, v.y), fmaxf(v.z, v.w)));
    }

    __shared__ float redmax[8];
    __shared__ float redsum[8];

    #pragma unroll
    for (int o = 16; o; o >>= 1) m = fmaxf(m, __shfl_xor_sync(0xffffffffu, m, o));
    if ((t & 31) == 0) redmax[t >> 5] = m;
    __syncthreads();
    m = redmax[0];
    #pragma unroll
    for (int i = 1; i < 8; i++) m = fmaxf(m, redmax[i]);

    float s = 0.0f;
    #pragma unroll
    for (int i = 0; i < 16; i++) { buf[i] = expf(buf[i] - m); s += buf[i]; }

    #pragma unroll
    for (int o = 16; o; o >>= 1) s += __shfl_xor_sync(0xffffffffu, s, o);
    if ((t & 31) == 0) redsum[t >> 5] = s;
    __syncthreads();
    s = 0.0f;
    #pragma unroll
    for (int i = 0; i < 8; i++) s += redsum[i];
    const float inv = 1.0f / s;

    #pragma unroll
    for (int c = 0; c < 4; c++) {
        float4 v;
        v.x = buf[c * 4 + 0] * inv; v.y = buf[c * 4 + 1] * inv;
        v.z = buf[c * 4 + 2] * inv; v.w = buf[c * 4 + 3] * inv;
        *(float4*)(p + c * 1024 + t * 4) = v;
    }
}

__global__ __launch_bounds__(256)
void context_partial(const float* __restrict__ kv, float* __restrict__ part)
{
    const int chunk = blockIdx.x;
    const int bh = blockIdx.y;
    const int b = bh >> 3, h = bh & 7;
    const float* kb = kv + (size_t)b * (2 * HID * LDIM) + (size_t)(h * 64) * LDIM + chunk * 512;
    const float* vb = kv + (size_t)b * (2 * HID * LDIM) + (size_t)(HID + h * 64) * LDIM + chunk * 512;

    __shared__ __align__(16) float Ks[32][68];
    __shared__ __align__(16) float Vs[32][68];

    const int t = threadIdx.x;
    const int tx = t & 15, ty = t >> 4;
    float acc[4][4] = {};

    for (int n0 = 0; n0 < 512; n0 += 32) {
        #pragma unroll
        for (int r = 0; r < 2; r++) {
            const int idx = t + r * 256;
            const int d = idx >> 3;
            const int nf = idx & 7;
            float4 kvv = *(const float4*)(kb + (size_t)d * LDIM + n0 + nf * 4);
            Ks[nf * 4 + 0][d] = kvv.x; Ks[nf * 4 + 1][d] = kvv.y;
            Ks[nf * 4 + 2][d] = kvv.z; Ks[nf * 4 + 3][d] = kvv.w;
            float4 vv = *(const float4*)(vb + (size_t)d * LDIM + n0 + nf * 4);
            Vs[nf * 4 + 0][d] = vv.x; Vs[nf * 4 + 1][d] = vv.y;
            Vs[nf * 4 + 2][d] = vv.z; Vs[nf * 4 + 3][d] = vv.w;
        }
        __syncthreads();
        #pragma unroll
        for (int kk = 0; kk < 32; kk++) {
            float ra[4], rb[4];
            *(float4*)ra = *(const float4*)(&Ks[kk][ty * 4]);
            *(float4*)rb = *(const float4*)(&Vs[kk][tx * 4]);
            #pragma unroll
            for (int i = 0; i < 4; i++)
                #pragma unroll
                for (int j = 0; j < 4; j++)
                    acc[i][j] = fmaf(ra[i], rb[j], acc[i][j]);
        }
        __syncthreads();
    }

    float* pp = part + (size_t)(chunk * 64 + bh) * (DIMH * DIMH);
    #pragma unroll
    for (int i = 0; i < 4; i++)
        #pragma unroll
        for (int j = 0; j < 4; j++)
            pp[(ty * 4 + i) * 64 + tx * 4 + j] = acc[i][j];
}

__global__ void context_reduce(const float* __restrict__ part, float* __restrict__ ctx)
{
    const int bh = blockIdx.x;
    for (int i = threadIdx.x; i < DIMH * DIMH; i += blockDim.x) {
        float s = 0.0f;
        #pragma unroll
        for (int c = 0; c < 8; c++) s += part[(size_t)(c * 64 + bh) * (DIMH * DIMH) + i];
        ctx[(size_t)bh * (DIMH * DIMH) + i] = s;
    }
}

// A_bT[c][(h,e)] = sum_d ctx[b,h,d,e] * W_q[(h,d),c]  -> fp16 [b][c][hid]
__global__ __launch_bounds__(256)
void make_Ab(const float* __restrict__ ctx, const float* __restrict__ w_qkv,
             __half* __restrict__ Abt)
{
    const int cc = blockIdx.x;    // c chunk of 64
    const int bh = blockIdx.y;
    const int b = bh >> 3, h = bh & 7;

    __shared__ float Cs[64 * 64];
    __shared__ float Ws[64][65];

    const int t = threadIdx.x;
    const float* cp = ctx + (size_t)bh * (DIMH * DIMH);
    for (int i = t; i < 4096; i += 256) Cs[i] = cp[i];
    for (int i = t; i < 4096; i += 256) {
        const int d = i >> 6, c = i & 63;
        Ws[d][c] = w_qkv[(size_t)(h * 64 + d) * CDIM + cc * 64 + c];
    }
    __syncthreads();

    for (int i = t; i < 4096; i += 256) {
        const int c = i >> 6, e = i & 63;   // e fastest -> coalesced Abt writes
        float s = 0.0f;
        #pragma unroll 8
        for (int d = 0; d < 64; d++) s = fmaf(Cs[d * 64 + e], Ws[d][c], s);
        Abt[(size_t)b * (CDIM * HID) + (size_t)(cc * 64 + c) * HID + h * 64 + e]
            = __float2half_rn(s);
    }
}

// ---------------------------------------------------------------------------
// Launch
// ---------------------------------------------------------------------------
extern "C" void kernel_launch(void* const* d_in, const int* in_sizes, int n_in,
                              void* d_out, int out_size)
{
    const float* x     = (const float*)d_in[0];   // (8, 512, 4096)
    const float* w_qkv = (const float*)d_in[1];   // (1536, 512)
    const float* w_out = (const float*)d_in[2];   // (512, 512)
    const float* b_out = (const float*)d_in[3];   // (512,)
    float* out = (float*)d_out;                   // (8, 512, 4096)

    float *kv, *part, *ctx;
    __half *xT, *wkh, *wkl, *woh, *wol, *Abt, *Mbh, *Mbl;
    cudaGetSymbolAddress((void**)&kv,   g_kv);
    cudaGetSymbolAddress((void**)&part, g_part);
    cudaGetSymbolAddress((void**)&ctx,  g_ctx);
    cudaGetSymbolAddress((void**)&xT,   g_xT);
    cudaGetSymbolAddress((void**)&wkh,  g_wk_h);
    cudaGetSymbolAddress((void**)&wkl,  g_wk_l);
    cudaGetSymbolAddress((void**)&woh,  g_wo_h);
    cudaGetSymbolAddress((void**)&wol,  g_wo_l);
    cudaGetSymbolAddress((void**)&Abt,  g_Abt);
    cudaGetSymbolAddress((void**)&Mbh,  g_Mb_h);
    cudaGetSymbolAddress((void**)&Mbl,  g_Mb_l);

    cudaFuncSetAttribute(tc2<0>, cudaFuncAttributeMaxDynamicSharedMemorySize, TC_SMEM);
    cudaFuncSetAttribute(tc2<1>, cudaFuncAttributeMaxDynamicSharedMemorySize, TC_SMEM);

    const dim3 blk(256);
    const long sX  = (long)CDIM * LDIM;
    const long sXT = (long)LDIM * CDIM;

    // 0) conversions
    conv_wsplit<<<(2 * HID * CDIM + 255) / 256, blk>>>(
        w_qkv + (size_t)HID * CDIM, wkh, wkl, 2 * HID * CDIM);
    conv_wsplit<<<(CDIM * HID + 255) / 256, blk>>>(w_out, woh, wol, CDIM * HID);
    conv_xT<<<dim3(LDIM / 32, CDIM / 32, BATCH), blk>>>(x, xT);

    // 1) kv[b] = W_kv @ x_b   (acc = 64*kv -> /64)
    tc2<0><<<dim3(LDIM / 256, (2 * HID) / 128, BATCH), blk, TC_SMEM>>>(
        wkh, wkl, 0L, xT, sXT, kv, nullptr, nullptr,
        (long)(2 * HID) * LDIM, LDIM, nullptr, 1.0f / 64.0f, 0.0f);

    // 2) softmax over L on k rows
    softmax_k<<<dim3(HID, BATCH), blk>>>(kv);

    // 3) context
    context_partial<<<dim3(8, 64), blk>>>(kv, part);
    context_reduce<<<64, blk>>>(part, ctx);

    // 4) A_b^T (fp16)
    make_Ab<<<dim3(8, 64), blk>>>(ctx, w_qkv, Abt);

    // 5) M_b = w_out @ A_b  (acc = 64*M_b; emit fp16 split of 2048*M_b)
    tc2<1><<<dim3(CDIM / 256, CDIM / 128, BATCH), blk, TC_SMEM>>>(
        woh, wol, 0L, Abt, (long)CDIM * HID, nullptr, Mbh, Mbl,
        (long)CDIM * CDIM, CDIM, nullptr, 0.0f, 32.0f);

    // 6) out[b] = M_b @ x_b + b_out  (acc = 2048*out -> /2048 + bias)
    tc2<0><<<dim3(LDIM / 256, CDIM / 128, BATCH), blk, TC_SMEM>>>(
        Mbh, Mbl, (long)CDIM * CDIM, xT, sXT, out, nullptr, nullptr,
        sX, LDIM, b_out, 1.0f / 2048.0f, 0.0f);
}

// round 5
// speedup vs baseline: 3.2898x; 1.1623x over previous
#include <cuda_runtime.h>
#include <cuda_fp16.h>
#include <math.h>
#include <stdint.h>

// Problem constants
#define BATCH 8
#define CDIM  512
#define LDIM  4096
#define HEADS 8
#define DIMH  64
#define HID   512   // HEADS*DIMH

// ---------------------------------------------------------------------------
// Scratch (static __device__ arrays)
// ---------------------------------------------------------------------------
__device__ float  g_k  [(size_t)BATCH * HID * LDIM];      // fp32 k logits [b][512][4096]
__device__ __half g_kh [(size_t)BATCH * HID * LDIM];      // fp16 softmaxed k
__device__ __half g_v  [(size_t)BATCH * HID * LDIM];      // fp16 v
__device__ float  g_part[(size_t)4 * 64 * DIMH * DIMH];   // context split-K partials
__device__ float  g_ctx [(size_t)64 * DIMH * DIMH];       // context [bh][d*64+e]

__device__ __half g_xT  [(size_t)BATCH * LDIM * CDIM];    // fp16(x)^T [b][l][c]
__device__ __half g_wk_h[(size_t)(2 * HID) * CDIM];       // fp16(64*W_kv) hi
__device__ __half g_wk_l[(size_t)(2 * HID) * CDIM];       // lo
__device__ __half g_wo_h[(size_t)CDIM * HID];             // fp16(64*W_out) hi
__device__ __half g_wo_l[(size_t)CDIM * HID];
__device__ __half g_Abt [(size_t)BATCH * CDIM * HID];     // fp16(A_b^T) [b][c][hid]
__device__ __half g_Mb_h[(size_t)BATCH * CDIM * CDIM];    // fp16(2048*M_b) hi
__device__ __half g_Mb_l[(size_t)BATCH * CDIM * CDIM];    // lo

// ---------------------------------------------------------------------------
// PTX helpers
// ---------------------------------------------------------------------------
__device__ __forceinline__ uint32_t smem_u32(const void* p) {
    uint32_t a;
    asm("{ .reg .u64 t; cvta.to.shared.u64 t, %1; cvt.u32.u64 %0, t; }" : "=r"(a) : "l"(p));
    return a;
}
__device__ __forceinline__ void cp_async16(uint32_t dst, const void* src) {
    asm volatile("cp.async.cg.shared.global [%0], [%1], 16;" :: "r"(dst), "l"(src));
}
__device__ __forceinline__ void cp_commit() { asm volatile("cp.async.commit_group;" ::: "memory"); }
__device__ __forceinline__ void cp_wait1()  { asm volatile("cp.async.wait_group 1;" ::: "memory"); }
__device__ __forceinline__ void cp_wait0()  { asm volatile("cp.async.wait_group 0;" ::: "memory"); }
__device__ __forceinline__ void ldsm_x4(uint32_t* r, uint32_t addr) {
    asm volatile("ldmatrix.sync.aligned.m8n8.x4.shared.b16 {%0,%1,%2,%3}, [%4];"
                 : "=r"(r[0]), "=r"(r[1]), "=r"(r[2]), "=r"(r[3]) : "r"(addr));
}
__device__ __forceinline__ void mma_fp16(float* c, const uint32_t* a, const uint32_t* b) {
    asm volatile(
        "mma.sync.aligned.m16n8k16.row.col.f32.f16.f16.f32 "
        "{%0,%1,%2,%3}, {%4,%5,%6,%7}, {%8,%9}, {%0,%1,%2,%3};"
        : "+f"(c[0]), "+f"(c[1]), "+f"(c[2]), "+f"(c[3])
        : "r"(a[0]), "r"(a[1]), "r"(a[2]), "r"(a[3]), "r"(b[0]), "r"(b[1]));
}

// ---------------------------------------------------------------------------
// tc2: C[b][m][n] = sum_k (Ah+Al)[m,k] * Bh[n,k]   (fp16 2-term, K=512)
// CTA tile 128x256, K-chunk 64, 3-stage cp.async pipeline, 8 warps (2Mx4N).
// MODE 0: fp32 out = acc*invScale (+bias)
// MODE 1: fp16 hi/lo split of acc*hScale
// MODE 2: GEMM1 — CTAs with m0<512 write fp32 k (acc*invScale);
//                 m0>=512 write fp16 v (acc*invScale) at row-512.
// ---------------------------------------------------------------------------
#define ROWB   144
#define A_MAT  (128 * ROWB)          // 18432
#define B_MAT  (256 * ROWB)          // 36864
#define STAGE  (2 * A_MAT + B_MAT)   // 73728
#define TC_SMEM (3 * STAGE)          // 221184

template<int MODE>
__global__ __launch_bounds__(256, 1)
void tc2(const __half* __restrict__ Ah, const __half* __restrict__ Al, long aBatch,
         const __half* __restrict__ Bh, long bBatch,
         float* __restrict__ Cf, __half* __restrict__ Ch, __half* __restrict__ Cl,
         long cBatch, int cRow,
         const float* __restrict__ bias, float invScale, float hScale)
{
    extern __shared__ char smem[];
    const uint32_t sb = smem_u32(smem);
    const int t = threadIdx.x;
    const int lane = t & 31;
    const int warp = t >> 5;
    const int wm = (warp & 1) * 64;
    const int wn = (warp >> 1) * 64;
    const int n0 = blockIdx.x * 256;
    const int m0 = blockIdx.y * 128;
    const int b = blockIdx.z;

    Ah += (size_t)b * aBatch;  Al += (size_t)b * aBatch;
    Bh += (size_t)b * bBatch;

    const uint32_t aOff = (uint32_t)((lane & 15) * ROWB + (lane >> 4) * 16);
    const uint32_t bOff = (uint32_t)(((lane & 7) + ((lane >> 4) << 3)) * ROWB
                                     + (((lane >> 3) & 1) * 16));

    float acc[4][8][4] = {};

    auto load_chunk = [&](int c, int buf) {
        const int k0 = c * 64;
        const uint32_t base = sb + (uint32_t)buf * STAGE;
        #pragma unroll
        for (int i = 0; i < 4; i++) {
            const int idx = t + i * 256;
            const int r = idx >> 3, s = idx & 7;
            const uint32_t dst = base + (uint32_t)(r * ROWB + s * 16);
            const size_t ga = (size_t)(m0 + r) * 512 + k0 + s * 8;
            cp_async16(dst,         Ah + ga);
            cp_async16(dst + A_MAT, Al + ga);
        }
        #pragma unroll
        for (int i = 0; i < 8; i++) {
            const int idx = t + i * 256;
            const int r = idx >> 3, s = idx & 7;
            const uint32_t dst = base + 2 * A_MAT + (uint32_t)(r * ROWB + s * 16);
            cp_async16(dst, Bh + (size_t)(n0 + r) * 512 + k0 + s * 8);
        }
    };

    load_chunk(0, 0); cp_commit();
    load_chunk(1, 1); cp_commit();

    for (int c = 0; c < 8; c++) {
        if (c < 7) cp_wait1(); else cp_wait0();
        __syncthreads();
        if (c < 6) { load_chunk(c + 2, (c + 2) % 3); cp_commit(); }

        const uint32_t base = sb + (uint32_t)(c % 3) * STAGE;
        #pragma unroll
        for (int ks = 0; ks < 4; ks++) {
            const uint32_t kb = (uint32_t)(ks * 32);
            uint32_t ah[4][4], al[4][4];
            #pragma unroll
            for (int mt = 0; mt < 4; mt++) {
                const uint32_t ra = base + (uint32_t)((wm + mt * 16) * ROWB) + aOff + kb;
                ldsm_x4(ah[mt], ra);
                ldsm_x4(al[mt], ra + A_MAT);
            }
            uint32_t bfr[8][2];
            #pragma unroll
            for (int np = 0; np < 4; np++) {
                uint32_t r4[4];
                const uint32_t rb = base + 2 * A_MAT
                    + (uint32_t)((wn + np * 16) * ROWB) + bOff + kb;
                ldsm_x4(r4, rb);
                bfr[np * 2][0] = r4[0]; bfr[np * 2][1] = r4[1];
                bfr[np * 2 + 1][0] = r4[2]; bfr[np * 2 + 1][1] = r4[3];
            }
            #pragma unroll
            for (int mt = 0; mt < 4; mt++)
                #pragma unroll
                for (int nt = 0; nt < 8; nt++) {
                    mma_fp16(acc[mt][nt], ah[mt], bfr[nt]);
                    mma_fp16(acc[mt][nt], al[mt], bfr[nt]);
                }
        }
        __syncthreads();
    }

    // ---- epilogue ----
    #pragma unroll
    for (int mt = 0; mt < 4; mt++) {
        const int row = m0 + wm + mt * 16 + (lane >> 2);
        float bv0 = 0.0f, bv1 = 0.0f;
        if (MODE == 0 && bias) { bv0 = bias[row]; bv1 = bias[row + 8]; }
        #pragma unroll
        for (int nt = 0; nt < 8; nt++) {
            const int col = n0 + wn + nt * 8 + 2 * (lane & 3);
            if (MODE == 0) {
                float* c0 = Cf + (size_t)b * cBatch + (size_t)row * cRow + col;
                float* c1 = Cf + (size_t)b * cBatch + (size_t)(row + 8) * cRow + col;
                *(float2*)c0 = make_float2(acc[mt][nt][0] * invScale + bv0,
                                           acc[mt][nt][1] * invScale + bv0);
                *(float2*)c1 = make_float2(acc[mt][nt][2] * invScale + bv1,
                                           acc[mt][nt][3] * invScale + bv1);
            } else if (MODE == 1) {
                #pragma unroll
                for (int hf = 0; hf < 2; hf++) {
                    const int rr = row + hf * 8;
                    const float v0 = acc[mt][nt][hf * 2 + 0] * hScale;
                    const float v1 = acc[mt][nt][hf * 2 + 1] * hScale;
                    const __half h0 = __float2half_rn(v0);
                    const __half h1 = __float2half_rn(v1);
                    const __half l0 = __float2half_rn(v0 - __half2float(h0));
                    const __half l1 = __float2half_rn(v1 - __half2float(h1));
                    const size_t o = (size_t)b * cBatch + (size_t)rr * cRow + col;
                    *(__half2*)(Ch + o) = __halves2half2(h0, h1);
                    *(__half2*)(Cl + o) = __halves2half2(l0, l1);
                }
            } else {  // MODE 2: k fp32 / v fp16
                if (m0 < 512) {
                    float* c0 = Cf + (size_t)b * cBatch + (size_t)row * cRow + col;
                    float* c1 = Cf + (size_t)b * cBatch + (size_t)(row + 8) * cRow + col;
                    *(float2*)c0 = make_float2(acc[mt][nt][0] * invScale,
                                               acc[mt][nt][1] * invScale);
                    *(float2*)c1 = make_float2(acc[mt][nt][2] * invScale,
                                               acc[mt][nt][3] * invScale);
                } else {
                    #pragma unroll
                    for (int hf = 0; hf < 2; hf++) {
                        const int rr = row - 512 + hf * 8;
                        const float v0 = acc[mt][nt][hf * 2 + 0] * invScale;
                        const float v1 = acc[mt][nt][hf * 2 + 1] * invScale;
                        const size_t o = (size_t)b * cBatch + (size_t)rr * cRow + col;
                        *(__half2*)(Ch + o) =
                            __halves2half2(__float2half_rn(v0), __float2half_rn(v1));
                    }
                }
            }
        }
    }
}

// ---------------------------------------------------------------------------
// context_mma: part[sp][bh][d][e] = sum_{n in split sp} kh[d,n] * v[e,n]
// grid (4 splits, 64 bh), 256 threads, fp16 MMA, double-buffered cp.async.
// ---------------------------------------------------------------------------
#define CTX_ROWB 144
#define CTX_MAT  (64 * CTX_ROWB)        // 9216
#define CTX_STAGE (2 * CTX_MAT)         // 18432

__global__ __launch_bounds__(256)
void context_mma(const __half* __restrict__ kh, const __half* __restrict__ v,
                 float* __restrict__ part)
{
    __shared__ __align__(16) char smem[2 * CTX_STAGE];
    const uint32_t sb = smem_u32(smem);
    const int t = threadIdx.x;
    const int lane = t & 31;
    const int warp = t >> 5;
    const int wm = (warp & 1) * 32;
    const int wn = (warp >> 1) * 16;
    const int sp = blockIdx.x;      // K split 0..3
    const int bh = blockIdx.y;      // 0..63
    const int b = bh >> 3, h = bh & 7;

    const __half* ka = kh + (size_t)(b * HID + h * 64) * LDIM + sp * 1024;
    const __half* va = v  + (size_t)(b * HID + h * 64) * LDIM + sp * 1024;

    const uint32_t aOff = (uint32_t)((lane & 15) * CTX_ROWB + (lane >> 4) * 16);
    const uint32_t bOff = (uint32_t)(((lane & 7) + ((lane >> 4) << 3)) * CTX_ROWB
                                     + (((lane >> 3) & 1) * 16));

    float acc[2][2][4] = {};

    auto load_chunk = [&](int c, int buf) {
        const int k0 = c * 64;
        const uint32_t base = sb + (uint32_t)buf * CTX_STAGE;
        #pragma unroll
        for (int i = 0; i < 4; i++) {
            const int idx = t + i * 256;   // 0..1023
            const int mat = idx >> 9;      // 0=k, 1=v
            const int rr = (idx >> 3) & 63;
            const int s = idx & 7;
            const uint32_t dst = base + (uint32_t)(mat * CTX_MAT + rr * CTX_ROWB + s * 16);
            const __half* src = (mat == 0 ? ka : va) + (size_t)rr * LDIM + k0 + s * 8;
            cp_async16(dst, src);
        }
    };

    load_chunk(0, 0); cp_commit();

    for (int c = 0; c < 16; c++) {
        if (c < 15) { load_chunk(c + 1, (c + 1) & 1); cp_commit(); cp_wait1(); }
        else        { cp_wait0(); }
        __syncthreads();

        const uint32_t base = sb + (uint32_t)(c & 1) * CTX_STAGE;
        #pragma unroll
        for (int ks = 0; ks < 4; ks++) {
            const uint32_t kb = (uint32_t)(ks * 32);
            uint32_t a[2][4];
            #pragma unroll
            for (int mt = 0; mt < 2; mt++)
                ldsm_x4(a[mt], base + (uint32_t)((wm + mt * 16) * CTX_ROWB) + aOff + kb);
            uint32_t r4[4];
            ldsm_x4(r4, base + CTX_MAT + (uint32_t)(wn * CTX_ROWB) + bOff + kb);
            uint32_t bf[2][2] = {{r4[0], r4[1]}, {r4[2], r4[3]}};
            #pragma unroll
            for (int mt = 0; mt < 2; mt++)
                #pragma unroll
                for (int nt = 0; nt < 2; nt++)
                    mma_fp16(acc[mt][nt], a[mt], bf[nt]);
        }
        __syncthreads();
    }

    float* pp = part + (size_t)(sp * 64 + bh) * (DIMH * DIMH);
    #pragma unroll
    for (int mt = 0; mt < 2; mt++) {
        const int row = wm + mt * 16 + (lane >> 2);
        #pragma unroll
        for (int nt = 0; nt < 2; nt++) {
            const int col = wn + nt * 8 + 2 * (lane & 3);
            *(float2*)(pp + (size_t)row * 64 + col)
                = make_float2(acc[mt][nt][0], acc[mt][nt][1]);
            *(float2*)(pp + (size_t)(row + 8) * 64 + col)
                = make_float2(acc[mt][nt][2], acc[mt][nt][3]);
        }
    }
}

__global__ __launch_bounds__(256)
void ctx_reduce4(const float* __restrict__ part, float* __restrict__ ctx)
{
    const int i = blockIdx.x * 1024 + threadIdx.x * 4;
    float4 s = *(const float4*)(part + i);
    #pragma unroll
    for (int c = 1; c < 4; c++) {
        float4 p = *(const float4*)(part + (size_t)c * 64 * DIMH * DIMH + i);
        s.x += p.x; s.y += p.y; s.z += p.z; s.w += p.w;
    }
    *(float4*)(ctx + i) = s;
}

// ---------------------------------------------------------------------------
// Conversions
// ---------------------------------------------------------------------------
__global__ __launch_bounds__(256)
void conv_wsplit(const float* __restrict__ in, __half* __restrict__ hi,
                 __half* __restrict__ lo, int n)
{
    int i = blockIdx.x * 256 + threadIdx.x;
    if (i >= n) return;
    float v = in[i] * 64.0f;
    __half h = __float2half_rn(v);
    hi[i] = h;
    lo[i] = __float2half_rn(v - __half2float(h));
}

__global__ __launch_bounds__(256)
void conv_xT(const float* __restrict__ x, __half* __restrict__ xh)
{
    __shared__ float tile[32][33];
    const int l0 = blockIdx.x * 32, c0 = blockIdx.y * 32, b = blockIdx.z;
    const float* xb = x + (size_t)b * CDIM * LDIM;
    const int tr = threadIdx.x >> 5;
    const int tc = threadIdx.x & 31;

    #pragma unroll
    for (int i = 0; i < 4; i++) {
        const int c = tr + i * 8;
        tile[c][tc] = xb[(size_t)(c0 + c) * LDIM + l0 + tc];
    }
    __syncthreads();

    __half* oh = xh + (size_t)b * LDIM * CDIM;
    #pragma unroll
    for (int i = 0; i < 4; i++) {
        const int l = tr + i * 8;
        oh[(size_t)(l0 + l) * CDIM + c0 + tc] = __float2half_rn(tile[tc][l]);
    }
}

// ---------------------------------------------------------------------------
// softmax over L, fp32 in -> fp16 out. grid (512, BATCH), 256 threads.
// ---------------------------------------------------------------------------
__global__ __launch_bounds__(256)
void softmax_k(const float* __restrict__ kin, __half* __restrict__ kout)
{
    const size_t off = (size_t)blockIdx.y * (HID * LDIM) + (size_t)blockIdx.x * LDIM;
    const float* p = kin + off;
    __half* q = kout + off;
    const int t = threadIdx.x;

    float buf[16];
    float m = -1e30f;
    #pragma unroll
    for (int c = 0; c < 4; c++) {
        float4 v = *(const float4*)(p + c * 1024 + t * 4);
        buf[c * 4 + 0] = v.x; buf[c * 4 + 1] = v.y;
        buf[c * 4 + 2] = v.z; buf[c * 4 + 3] = v.w;
        m = fmaxf(m, fmaxf(fmaxf(v.x, v.y), fmaxf(v.z, v.w)));
    }

    __shared__ float redmax[8];
    __shared__ float redsum[8];

    #pragma unroll
    for (int o = 16; o; o >>= 1) m = fmaxf(m, __shfl_xor_sync(0xffffffffu, m, o));
    if ((t & 31) == 0) redmax[t >> 5] = m;
    __syncthreads();
    m = redmax[0];
    #pragma unroll
    for (int i = 1; i < 8; i++) m = fmaxf(m, redmax[i]);

    float s = 0.0f;
    #pragma unroll
    for (int i = 0; i < 16; i++) { buf[i] = expf(buf[i] - m); s += buf[i]; }

    #pragma unroll
    for (int o = 16; o; o >>= 1) s += __shfl_xor_sync(0xffffffffu, s, o);
    if ((t & 31) == 0) redsum[t >> 5] = s;
    __syncthreads();
    s = 0.0f;
    #pragma unroll
    for (int i = 0; i < 8; i++) s += redsum[i];
    const float inv = 1.0f / s;

    #pragma unroll
    for (int c = 0; c < 4; c++) {
        __half2 h0 = __halves2half2(__float2half_rn(buf[c * 4 + 0] * inv),
                                    __float2half_rn(buf[c * 4 + 1] * inv));
        __half2 h1 = __halves2half2(__float2half_rn(buf[c * 4 + 2] * inv),
                                    __float2half_rn(buf[c * 4 + 3] * inv));
        *(__half2*)(q + c * 1024 + t * 4)     = h0;
        *(__half2*)(q + c * 1024 + t * 4 + 2) = h1;
    }
}

// ---------------------------------------------------------------------------
// make_Ab: A_bT[c][(h,e)] = sum_d ctx[b,h,d,e] * W_q[(h,d),c] -> fp16
// ---------------------------------------------------------------------------
__global__ __launch_bounds__(256)
void make_Ab(const float* __restrict__ ctx, const float* __restrict__ w_qkv,
             __half* __restrict__ Abt)
{
    const int cc = blockIdx.x;
    const int bh = blockIdx.y;
    const int b = bh >> 3, h = bh & 7;

    __shared__ float Cs[64 * 64];
    __shared__ float Ws[64][65];

    const int t = threadIdx.x;
    const float* cp = ctx + (size_t)bh * (DIMH * DIMH);
    for (int i = t; i < 4096; i += 256) Cs[i] = cp[i];
    for (int i = t; i < 4096; i += 256) {
        const int d = i >> 6, c = i & 63;
        Ws[d][c] = w_qkv[(size_t)(h * 64 + d) * CDIM + cc * 64 + c];
    }
    __syncthreads();

    for (int i = t; i < 4096; i += 256) {
        const int c = i >> 6, e = i & 63;
        float s = 0.0f;
        #pragma unroll 8
        for (int d = 0; d < 64; d++) s = fmaf(Cs[d * 64 + e], Ws[d][c], s);
        Abt[(size_t)b * (CDIM * HID) + (size_t)(cc * 64 + c) * HID + h * 64 + e]
            = __float2half_rn(s);
    }
}

// ---------------------------------------------------------------------------
// Launch
// ---------------------------------------------------------------------------
extern "C" void kernel_launch(void* const* d_in, const int* in_sizes, int n_in,
                              void* d_out, int out_size)
{
    const float* x     = (const float*)d_in[0];
    const float* w_qkv = (const float*)d_in[1];
    const float* w_out = (const float*)d_in[2];
    const float* b_out = (const float*)d_in[3];
    float* out = (float*)d_out;

    float *k32, *part, *ctx;
    __half *kh, *v16, *xT, *wkh, *wkl, *woh, *wol, *Abt, *Mbh, *Mbl;
    cudaGetSymbolAddress((void**)&k32,  g_k);
    cudaGetSymbolAddress((void**)&kh,   g_kh);
    cudaGetSymbolAddress((void**)&v16,  g_v);
    cudaGetSymbolAddress((void**)&part, g_part);
    cudaGetSymbolAddress((void**)&ctx,  g_ctx);
    cudaGetSymbolAddress((void**)&xT,   g_xT);
    cudaGetSymbolAddress((void**)&wkh,  g_wk_h);
    cudaGetSymbolAddress((void**)&wkl,  g_wk_l);
    cudaGetSymbolAddress((void**)&woh,  g_wo_h);
    cudaGetSymbolAddress((void**)&wol,  g_wo_l);
    cudaGetSymbolAddress((void**)&Abt,  g_Abt);
    cudaGetSymbolAddress((void**)&Mbh,  g_Mb_h);
    cudaGetSymbolAddress((void**)&Mbl,  g_Mb_l);

    cudaFuncSetAttribute(tc2<0>, cudaFuncAttributeMaxDynamicSharedMemorySize, TC_SMEM);
    cudaFuncSetAttribute(tc2<1>, cudaFuncAttributeMaxDynamicSharedMemorySize, TC_SMEM);
    cudaFuncSetAttribute(tc2<2>, cudaFuncAttributeMaxDynamicSharedMemorySize, TC_SMEM);

    const dim3 blk(256);
    const long sX  = (long)CDIM * LDIM;
    const long sXT = (long)LDIM * CDIM;
    const long sK  = (long)HID * LDIM;

    // 0) conversions
    conv_wsplit<<<(2 * HID * CDIM + 255) / 256, blk>>>(
        w_qkv + (size_t)HID * CDIM, wkh, wkl, 2 * HID * CDIM);
    conv_wsplit<<<(CDIM * HID + 255) / 256, blk>>>(w_out, woh, wol, CDIM * HID);
    conv_xT<<<dim3(LDIM / 32, CDIM / 32, BATCH), blk>>>(x, xT);

    // 1) GEMM1: k (fp32) + v (fp16) = W_kv @ x_b
    tc2<2><<<dim3(LDIM / 256, (2 * HID) / 128, BATCH), blk, TC_SMEM>>>(
        wkh, wkl, 0L, xT, sXT, k32, v16, nullptr,
        sK, LDIM, nullptr, 1.0f / 64.0f, 0.0f);

    // 2) softmax: k fp32 -> k̂ fp16
    softmax_k<<<dim3(HID, BATCH), blk>>>(k32, kh);

    // 3) context (tensor core, split-K 4) + reduce
    context_mma<<<dim3(4, 64), blk>>>(kh, v16, part);
    ctx_reduce4<<<(64 * DIMH * DIMH) / 1024, blk>>>(part, ctx);

    // 4) A_b^T fp16
    make_Ab<<<dim3(8, 64), blk>>>(ctx, w_qkv, Abt);

    // 5) M_b = w_out @ A_b -> fp16 split of 2048*M_b
    tc2<1><<<dim3(CDIM / 256, CDIM / 128, BATCH), blk, TC_SMEM>>>(
        woh, wol, 0L, Abt, (long)CDIM * HID, nullptr, Mbh, Mbl,
        (long)CDIM * CDIM, CDIM, nullptr, 0.0f, 32.0f);

    // 6) out = M_b @ x_b + b_out
    tc2<0><<<dim3(LDIM / 256, CDIM / 128, BATCH), blk, TC_SMEM>>>(
        Mbh, Mbl, (long)CDIM * CDIM, xT, sXT, out, nullptr, nullptr,
        sX, LDIM, b_out, 1.0f / 2048.0f, 0.0f);
}